// round 7
// baseline (speedup 1.0000x reference)
#include <cuda_runtime.h>
#include <math.h>

// Problem constants
#define SDIM   2048
#define DIN    1024
#define NH     16
#define DH     64
#define BTOT   4
#define MROWS  (BTOT * SDIM)   // 8192
#define PAIRS  (DIN / 2)       // 512 k-pairs per row
#define SCALE  0.125f          // 1/sqrt(64), exact power of 2

// ---------------- scratch (no cudaMalloc allowed) ----------------
// pre-split activations (query/key/value), bf16x2 pair planes
__device__ unsigned g_actH[3u * MROWS * PAIRS];
__device__ unsigned g_actL[3u * MROWS * PAIRS];
// pre-split weights (Wq,Wk,Wv,Wo) in [kpair][n] layout
__device__ unsigned g_wH[4u * PAIRS * DIN];
__device__ unsigned g_wL[4u * PAIRS * DIN];
// projected Q,K: split bf16 pair planes (Q pre-scaled by SCALE)
__device__ unsigned g_Qh[MROWS * PAIRS];
__device__ unsigned g_Ql[MROWS * PAIRS];
__device__ unsigned g_Kh[MROWS * PAIRS];
__device__ unsigned g_Kl[MROWS * PAIRS];
// projected V, pre-rounded to tf32 bits
__device__ unsigned g_Vt[MROWS * DIN];
// attention output, split bf16 pair planes
__device__ unsigned g_AOh[MROWS * PAIRS];
__device__ unsigned g_AOl[MROWS * PAIRS];

// ---------------- precision helpers ----------------
__device__ __forceinline__ unsigned f2tf(float f) {
    unsigned u;
    asm("cvt.rna.tf32.f32 %0, %1;" : "=r"(u) : "f"(f));
    return u;
}
// pack two floats as bf16x2: e0 -> low half (even k), e1 -> high half (odd k)
__device__ __forceinline__ unsigned bfpack(float e0, float e1) {
    unsigned u;
    asm("cvt.rn.bf16x2.f32 %0, %1, %2;" : "=r"(u) : "f"(e1), "f"(e0));
    return u;
}
// split (e0,e1) into hi bf16x2 and lo (residual) bf16x2
__device__ __forceinline__ void bfsplit2(float e0, float e1, unsigned& hi, unsigned& lo) {
    hi = bfpack(e0, e1);
    float h0 = __uint_as_float((hi & 0x0000ffffu) << 16);
    float h1 = __uint_as_float(hi & 0xffff0000u);
    lo = bfpack(e0 - h0, e1 - h1);
}

// D(16x8) += A(16x8) * B(8x8), tf32, fp32 accum
__device__ __forceinline__ void mma8(float* c,
    unsigned a0, unsigned a1, unsigned a2, unsigned a3,
    unsigned b0, unsigned b1)
{
    asm volatile(
        "mma.sync.aligned.m16n8k8.row.col.f32.tf32.tf32.f32 "
        "{%0,%1,%2,%3}, {%4,%5,%6,%7}, {%8,%9}, {%0,%1,%2,%3};"
        : "+f"(c[0]), "+f"(c[1]), "+f"(c[2]), "+f"(c[3])
        : "r"(a0), "r"(a1), "r"(a2), "r"(a3), "r"(b0), "r"(b1));
}
// D(16x8) += A(16x16) * B(16x8), bf16, fp32 accum
__device__ __forceinline__ void mma16(float* c,
    unsigned a0, unsigned a1, unsigned a2, unsigned a3,
    unsigned b0, unsigned b1)
{
    asm volatile(
        "mma.sync.aligned.m16n8k16.row.col.f32.bf16.bf16.f32 "
        "{%0,%1,%2,%3}, {%4,%5,%6,%7}, {%8,%9}, {%0,%1,%2,%3};"
        : "+f"(c[0]), "+f"(c[1]), "+f"(c[2]), "+f"(c[3])
        : "r"(a0), "r"(a1), "r"(a2), "r"(a3), "r"(b0), "r"(b1));
}

// ============================================================================
// Preprocess 1: split f32 activation [MROWS][DIN] -> bf16x2 hi/lo pair planes
// grid 8192 x 256 threads, one float4 (= 2 pairs) per thread
// ============================================================================
__global__ __launch_bounds__(256) void split_act(const float* __restrict__ src, int plane)
{
    size_t i = (size_t)blockIdx.x * 256 + threadIdx.x;     // float4 index
    float4 v = ((const float4*)src)[i];
    unsigned h0, l0, h1, l1;
    bfsplit2(v.x, v.y, h0, l0);
    bfsplit2(v.z, v.w, h1, l1);
    size_t o = (size_t)plane * MROWS * PAIRS + i * 2;
    *(uint2*)&g_actH[o] = make_uint2(h0, h1);
    *(uint2*)&g_actL[o] = make_uint2(l0, l1);
}

// ============================================================================
// Preprocess 2: split weights -> [kpair][n] hi/lo planes
// qkv=1: W is [H][DIN][DH]; pair (k,k+1) at n=h*64+d.  qkv=0: W is [DIN][DIN].
// grid 2048 x 256 (512*1024 elements)
// ============================================================================
__global__ __launch_bounds__(256) void split_w(const float* __restrict__ W, int sel, int qkv)
{
    int i  = blockIdx.x * 256 + threadIdx.x;
    int kp = i >> 10;
    int n  = i & 1023;
    float s0, s1;
    if (qkv) {
        int h = n >> 6, d = n & 63;
        const float* p = W + ((size_t)h * DIN + 2 * kp) * DH + d;
        s0 = p[0]; s1 = p[DH];
    } else {
        const float* p = W + (size_t)(2 * kp) * DIN + n;
        s0 = p[0]; s1 = p[DIN];
    }
    unsigned h, l;
    bfsplit2(s0, s1, h, l);
    g_wH[(size_t)sel * PAIRS * DIN + i] = h;
    g_wL[(size_t)sel * PAIRS * DIN + i] = l;
}

// ============================================================================
// split-bf16 GEMM (3-term 3xBF16 ~ fp32), operands pre-split in global.
// Block 128x128, BK=64 (32 pairs), 256 threads = 8 warps (2x4), warp 64x32.
// As [128][36] pairs (pad%8==4), Bs [32][136] (pad%32==8) -> conflict-free.
// aSel: 0..2 -> g_act plane, 3 -> g_AO.   wSel: 0..3.
// outMode: 0 Q(split+scale), 1 K(split), 2 V(tf32), 3 f32 -> C_ext
// ============================================================================
#define GAPAD 36
#define GBPAD 136
#define GSMEM ((128 * GAPAD * 2 + 32 * GBPAD * 2) * 4)   // 71680 B

__global__ __launch_bounds__(256, 2) void gemm_bf16(
    const float* __restrict__ bias, float* __restrict__ C_ext,
    int aSel, int wSel, int outMode)
{
    extern __shared__ unsigned gsm[];
    unsigned* AsH = gsm;                    // [128][GAPAD]
    unsigned* AsL = AsH + 128 * GAPAD;
    unsigned* BsH = AsL + 128 * GAPAD;      // [32][GBPAD]
    unsigned* BsL = BsH + 32 * GBPAD;

    const unsigned* Ah = (aSel < 3) ? g_actH + (size_t)aSel * MROWS * PAIRS : g_AOh;
    const unsigned* Al = (aSel < 3) ? g_actL + (size_t)aSel * MROWS * PAIRS : g_AOl;
    const unsigned* Bh = g_wH + (size_t)wSel * PAIRS * DIN;
    const unsigned* Bl = g_wL + (size_t)wSel * PAIRS * DIN;

    const int tid  = threadIdx.x;
    const int warp = tid >> 5;
    const int lane = tid & 31;
    const int grp  = lane >> 2;
    const int tig  = lane & 3;
    const int row0 = blockIdx.y * 128;
    const int col0 = blockIdx.x * 128;
    const int wm   = (warp >> 2) * 64;
    const int wn   = (warp & 3) * 32;

    float acc[4][4][4];
#pragma unroll
    for (int mf = 0; mf < 4; mf++)
#pragma unroll
        for (int nf = 0; nf < 4; nf++)
#pragma unroll
            for (int i = 0; i < 4; i++) acc[mf][nf][i] = 0.f;

    for (int kp0 = 0; kp0 < PAIRS; kp0 += 32) {   // 16 chunks of 64 k
        __syncthreads();
        // ---- copy A tile 128x32 pairs (both planes) ----
#pragma unroll
        for (int i = 0; i < 4; i++) {
            int idx = tid + i * 256;
            int r   = idx >> 3;
            int q4  = (idx & 7) << 2;
            size_t g = (size_t)(row0 + r) * PAIRS + kp0 + q4;
            *(uint4*)&AsH[r * GAPAD + q4] = *(const uint4*)&Ah[g];
            *(uint4*)&AsL[r * GAPAD + q4] = *(const uint4*)&Al[g];
        }
        // ---- copy B tile 32x128 (both planes) ----
#pragma unroll
        for (int i = 0; i < 4; i++) {
            int idx = tid + i * 256;
            int kr  = idx >> 5;
            int q4  = (idx & 31) << 2;
            size_t g = (size_t)(kp0 + kr) * DIN + col0 + q4;
            *(uint4*)&BsH[kr * GBPAD + q4] = *(const uint4*)&Bh[g];
            *(uint4*)&BsL[kr * GBPAD + q4] = *(const uint4*)&Bl[g];
        }
        __syncthreads();

        // ---- 4 ksteps of m16n8k16, 3-term ----
#pragma unroll
        for (int s = 0; s < 4; s++) {
            const int kb = s * 8;
            unsigned aH[4][4], aL[4][4];
#pragma unroll
            for (int mf = 0; mf < 4; mf++) {
                int m0 = (wm + mf * 16 + grp) * GAPAD;
                int m1 = m0 + 8 * GAPAD;
                aH[mf][0] = AsH[m0 + kb + tig];
                aH[mf][1] = AsH[m1 + kb + tig];
                aH[mf][2] = AsH[m0 + kb + tig + 4];
                aH[mf][3] = AsH[m1 + kb + tig + 4];
                aL[mf][0] = AsL[m0 + kb + tig];
                aL[mf][1] = AsL[m1 + kb + tig];
                aL[mf][2] = AsL[m0 + kb + tig + 4];
                aL[mf][3] = AsL[m1 + kb + tig + 4];
            }
#pragma unroll
            for (int nf = 0; nf < 4; nf++) {
                int n = wn + nf * 8 + grp;
                unsigned bH0 = BsH[(kb + tig    ) * GBPAD + n];
                unsigned bH1 = BsH[(kb + tig + 4) * GBPAD + n];
                unsigned bL0 = BsL[(kb + tig    ) * GBPAD + n];
                unsigned bL1 = BsL[(kb + tig + 4) * GBPAD + n];
#pragma unroll
                for (int mf = 0; mf < 4; mf++)
                    mma16(acc[mf][nf], aH[mf][0], aH[mf][1], aH[mf][2], aH[mf][3], bH0, bH1);
#pragma unroll
                for (int mf = 0; mf < 4; mf++)
                    mma16(acc[mf][nf], aH[mf][0], aH[mf][1], aH[mf][2], aH[mf][3], bL0, bL1);
#pragma unroll
                for (int mf = 0; mf < 4; mf++)
                    mma16(acc[mf][nf], aL[mf][0], aL[mf][1], aL[mf][2], aL[mf][3], bH0, bH1);
            }
        }
    }

    // ---- epilogue ----
#pragma unroll
    for (int nf = 0; nf < 4; nf++) {
        int c = col0 + wn + nf * 8 + 2 * tig;
        float bv0 = bias[c], bv1 = bias[c + 1];
#pragma unroll
        for (int mf = 0; mf < 4; mf++) {
            int r = row0 + wm + mf * 16 + grp;
            float p00 = acc[mf][nf][0] + bv0, p01 = acc[mf][nf][1] + bv1;   // row r
            float p10 = acc[mf][nf][2] + bv0, p11 = acc[mf][nf][3] + bv1;   // row r+8
            if (outMode == 0) {          // Q: scale + split
                unsigned h, l;
                bfsplit2(p00 * SCALE, p01 * SCALE, h, l);
                g_Qh[(size_t)r * PAIRS + (c >> 1)] = h;
                g_Ql[(size_t)r * PAIRS + (c >> 1)] = l;
                bfsplit2(p10 * SCALE, p11 * SCALE, h, l);
                g_Qh[(size_t)(r + 8) * PAIRS + (c >> 1)] = h;
                g_Ql[(size_t)(r + 8) * PAIRS + (c >> 1)] = l;
            } else if (outMode == 1) {   // K: split
                unsigned h, l;
                bfsplit2(p00, p01, h, l);
                g_Kh[(size_t)r * PAIRS + (c >> 1)] = h;
                g_Kl[(size_t)r * PAIRS + (c >> 1)] = l;
                bfsplit2(p10, p11, h, l);
                g_Kh[(size_t)(r + 8) * PAIRS + (c >> 1)] = h;
                g_Kl[(size_t)(r + 8) * PAIRS + (c >> 1)] = l;
            } else if (outMode == 2) {   // V: tf32 bits
                *(uint2*)&g_Vt[(size_t)r * DIN + c]       = make_uint2(f2tf(p00), f2tf(p01));
                *(uint2*)&g_Vt[(size_t)(r + 8) * DIN + c] = make_uint2(f2tf(p10), f2tf(p11));
            } else {                     // final f32 output
                *(float2*)(C_ext + (size_t)r * DIN + c)       = make_float2(p00, p01);
                *(float2*)(C_ext + (size_t)(r + 8) * DIN + c) = make_float2(p10, p11);
            }
        }
    }
}

// ============================================================================
// Flash attention: QK = split-bf16 3-term; PV = single tf32.
// All operands pre-converted in global; mainloop loads are raw uint4 copies.
// Block = (b,h) x 128-query tile, 256 thr, 8 warps; warp owns 16 q-rows.
// smem: QsH/L [128][36], KsH/L [64][36], Vs [64][72], Ps [128][68] = 108544 B
// ============================================================================
#define AQPAD 36
#define AKPAD 36
#define AVPAD 72
#define APPAD 68
#define ATTN_SMEM ((128 * AQPAD * 2 + 64 * AKPAD * 2 + 64 * AVPAD + 128 * APPAD) * 4)

__global__ __launch_bounds__(256, 2) void attn_bf16()
{
    extern __shared__ unsigned sm[];
    unsigned* QsH = sm;
    unsigned* QsL = QsH + 128 * AQPAD;
    unsigned* KsH = QsL + 128 * AQPAD;
    unsigned* KsL = KsH + 64 * AKPAD;
    unsigned* Vs  = KsL + 64 * AKPAD;
    unsigned* Ps  = Vs  + 64 * AVPAD;

    const int tid  = threadIdx.x;
    const int warp = tid >> 5;
    const int lane = tid & 31;
    const int grp  = lane >> 2;
    const int tig  = lane & 3;

    const int bh = blockIdx.y;
    const int b  = bh >> 4;
    const int h  = bh & 15;
    const int q0 = blockIdx.x * 128;
    const size_t base = (size_t)b * SDIM;
    const int coff  = h * DH;          // f32/tf32 column offset
    const int poff  = coff >> 1;       // pair column offset
    const int qw    = warp * 16;

    // ---- copy Q tile (pre-scaled, pre-split) ----
    for (int i = tid; i < 128 * 8; i += 256) {
        int r  = i >> 3;
        int q4 = (i & 7) << 2;
        size_t g = (base + q0 + r) * PAIRS + poff + q4;
        *(uint4*)&QsH[r * AQPAD + q4] = *(const uint4*)&g_Qh[g];
        *(uint4*)&QsL[r * AQPAD + q4] = *(const uint4*)&g_Ql[g];
    }

    float m0 = -1e30f, m1 = -1e30f, l0s = 0.f, l1s = 0.f;
    float O[8][4];
#pragma unroll
    for (int nf = 0; nf < 8; nf++)
#pragma unroll
        for (int i = 0; i < 4; i++) O[nf][i] = 0.f;

    for (int kk = 0; kk < SDIM; kk += 64) {
        __syncthreads();
        // ---- copy K (pairs) and V (tf32) chunk ----
        for (int i = tid; i < 64 * 8; i += 256) {
            int r  = i >> 3;
            int q4 = (i & 7) << 2;
            size_t g = (base + kk + r) * PAIRS + poff + q4;
            *(uint4*)&KsH[r * AKPAD + q4] = *(const uint4*)&g_Kh[g];
            *(uint4*)&KsL[r * AKPAD + q4] = *(const uint4*)&g_Kl[g];
        }
        for (int i = tid; i < 64 * 16; i += 256) {
            int r  = i >> 4;
            int q4 = (i & 15) << 2;
            *(uint4*)&Vs[r * AVPAD + q4] =
                *(const uint4*)&g_Vt[(base + kk + r) * DIN + coff + q4];
        }
        __syncthreads();

        // ---- S(16x64) = Q . K^T, bf16 3-term (4 k16-steps over DH=64) ----
        float S[8][4];
#pragma unroll
        for (int nf = 0; nf < 8; nf++)
#pragma unroll
            for (int i = 0; i < 4; i++) S[nf][i] = 0.f;

#pragma unroll
        for (int s = 0; s < 4; s++) {
            const int kb = s * 8;
            const int r0 = (qw + grp) * AQPAD;
            const int r1 = r0 + 8 * AQPAD;
            unsigned aH0 = QsH[r0 + kb + tig],     aH1 = QsH[r1 + kb + tig];
            unsigned aH2 = QsH[r0 + kb + tig + 4], aH3 = QsH[r1 + kb + tig + 4];
            unsigned aL0 = QsL[r0 + kb + tig],     aL1 = QsL[r1 + kb + tig];
            unsigned aL2 = QsL[r0 + kb + tig + 4], aL3 = QsL[r1 + kb + tig + 4];
#pragma unroll
            for (int nf = 0; nf < 8; nf++) {
                const int kr = (nf * 8 + grp) * AKPAD;
                unsigned bH0 = KsH[kr + kb + tig];
                unsigned bH1 = KsH[kr + kb + tig + 4];
                unsigned bL0 = KsL[kr + kb + tig];
                unsigned bL1 = KsL[kr + kb + tig + 4];
                mma16(S[nf], aH0, aH1, aH2, aH3, bH0, bH1);
                mma16(S[nf], aH0, aH1, aH2, aH3, bL0, bL1);
                mma16(S[nf], aL0, aL1, aL2, aL3, bH0, bH1);
            }
        }

        // ---- online softmax (rows qw+grp, qw+grp+8; 4 lanes/row) ----
        float mx0 = -1e30f, mx1 = -1e30f;
#pragma unroll
        for (int nf = 0; nf < 8; nf++) {
            mx0 = fmaxf(mx0, fmaxf(S[nf][0], S[nf][1]));
            mx1 = fmaxf(mx1, fmaxf(S[nf][2], S[nf][3]));
        }
        mx0 = fmaxf(mx0, __shfl_xor_sync(0xffffffffu, mx0, 1));
        mx0 = fmaxf(mx0, __shfl_xor_sync(0xffffffffu, mx0, 2));
        mx1 = fmaxf(mx1, __shfl_xor_sync(0xffffffffu, mx1, 1));
        mx1 = fmaxf(mx1, __shfl_xor_sync(0xffffffffu, mx1, 2));

        const float mn0 = fmaxf(m0, mx0);
        const float mn1 = fmaxf(m1, mx1);
        const float al0 = __expf(m0 - mn0);
        const float al1 = __expf(m1 - mn1);
        m0 = mn0; m1 = mn1;

        float rs0 = 0.f, rs1 = 0.f;
#pragma unroll
        for (int nf = 0; nf < 8; nf++) {
            float p0 = __expf(S[nf][0] - mn0);
            float p1 = __expf(S[nf][1] - mn0);
            float p2 = __expf(S[nf][2] - mn1);
            float p3 = __expf(S[nf][3] - mn1);
            rs0 += p0 + p1;
            rs1 += p2 + p3;
            const int cb = nf * 8 + 2 * tig;
            *(uint2*)&Ps[(qw + grp    ) * APPAD + cb] = make_uint2(f2tf(p0), f2tf(p1));
            *(uint2*)&Ps[(qw + grp + 8) * APPAD + cb] = make_uint2(f2tf(p2), f2tf(p3));
        }
        rs0 += __shfl_xor_sync(0xffffffffu, rs0, 1);
        rs0 += __shfl_xor_sync(0xffffffffu, rs0, 2);
        rs1 += __shfl_xor_sync(0xffffffffu, rs1, 1);
        rs1 += __shfl_xor_sync(0xffffffffu, rs1, 2);
        l0s = l0s * al0 + rs0;
        l1s = l1s * al1 + rs1;

#pragma unroll
        for (int nf = 0; nf < 8; nf++) {
            O[nf][0] *= al0; O[nf][1] *= al0;
            O[nf][2] *= al1; O[nf][3] *= al1;
        }
        __syncwarp();

        // ---- O(16x64) += P(16x64) . V(64x64), single tf32 ----
#pragma unroll
        for (int ks = 0; ks < 8; ks++) {
            const int kb = ks * 8;
            const int r0 = (qw + grp) * APPAD;
            const int r1 = r0 + 8 * APPAD;
            unsigned a0 = Ps[r0 + kb + tig],     a1 = Ps[r1 + kb + tig];
            unsigned a2 = Ps[r0 + kb + tig + 4], a3 = Ps[r1 + kb + tig + 4];
#pragma unroll
            for (int nf = 0; nf < 8; nf++) {
                unsigned b0 = Vs[(kb + tig    ) * AVPAD + nf * 8 + grp];
                unsigned b1 = Vs[(kb + tig + 4) * AVPAD + nf * 8 + grp];
                mma8(O[nf], a0, a1, a2, a3, b0, b1);
            }
        }
    }

    // ---- normalize + split-write AO ----
    const float inv0 = 1.f / l0s;
    const float inv1 = 1.f / l1s;
#pragma unroll
    for (int nf = 0; nf < 8; nf++) {
        const int c = coff + nf * 8 + 2 * tig;
        const size_t r0g = base + q0 + qw + grp;
        unsigned h, l;
        bfsplit2(O[nf][0] * inv0, O[nf][1] * inv0, h, l);
        g_AOh[r0g * PAIRS + (c >> 1)] = h;
        g_AOl[r0g * PAIRS + (c >> 1)] = l;
        bfsplit2(O[nf][2] * inv1, O[nf][3] * inv1, h, l);
        g_AOh[(r0g + 8) * PAIRS + (c >> 1)] = h;
        g_AOl[(r0g + 8) * PAIRS + (c >> 1)] = l;
    }
}

// ============================================================================
// launch
// ============================================================================
extern "C" void kernel_launch(void* const* d_in, const int* in_sizes, int n_in,
                              void* d_out, int out_size)
{
    (void)in_sizes; (void)n_in; (void)out_size;
    const float* q  = (const float*)d_in[0];
    const float* k  = (const float*)d_in[1];
    const float* v  = (const float*)d_in[2];
    const float* Wq = (const float*)d_in[3];
    const float* bq = (const float*)d_in[4];
    const float* Wk = (const float*)d_in[5];
    const float* bk = (const float*)d_in[6];
    const float* Wv = (const float*)d_in[7];
    const float* bv = (const float*)d_in[8];
    const float* Wo = (const float*)d_in[9];
    const float* bo = (const float*)d_in[10];
    float* out = (float*)d_out;

    cudaFuncSetAttribute(gemm_bf16,
                         cudaFuncAttributeMaxDynamicSharedMemorySize, GSMEM);
    cudaFuncSetAttribute(attn_bf16,
                         cudaFuncAttributeMaxDynamicSharedMemorySize, ATTN_SMEM);

    // --- preprocess: split activations & weights once ---
    split_act<<<MROWS * DIN / 4 / 256, 256>>>(q, 0);
    split_act<<<MROWS * DIN / 4 / 256, 256>>>(k, 1);
    split_act<<<MROWS * DIN / 4 / 256, 256>>>(v, 2);
    split_w<<<PAIRS * DIN / 256, 256>>>(Wq, 0, 1);
    split_w<<<PAIRS * DIN / 256, 256>>>(Wk, 1, 1);
    split_w<<<PAIRS * DIN / 256, 256>>>(Wv, 2, 1);
    split_w<<<PAIRS * DIN / 256, 256>>>(Wo, 3, 0);

    dim3 gg(DIN / 128, MROWS / 128);   // (8, 64)

    gemm_bf16<<<gg, 256, GSMEM>>>(bq, nullptr, 0, 0, 0);   // -> g_Qh/g_Ql (scaled)
    gemm_bf16<<<gg, 256, GSMEM>>>(bk, nullptr, 1, 1, 1);   // -> g_Kh/g_Kl
    gemm_bf16<<<gg, 256, GSMEM>>>(bv, nullptr, 2, 2, 2);   // -> g_Vt (tf32)

    attn_bf16<<<dim3(SDIM / 128, BTOT * NH), 256, ATTN_SMEM>>>();

    gemm_bf16<<<gg, 256, GSMEM>>>(bo, out, 3, 3, 3);       // -> d_out f32
}